// round 5
// baseline (speedup 1.0000x reference)
#include <cuda_runtime.h>
#include <cuda_bf16.h>

#define BATCH     1000000
#define FEAT      128
#define NCLASS    1000
#define NTHREADS  256
#define NBLOCKS   1184                      // 148 SMs * 8 blocks -> one full wave at ~32 regs
#define WARPS_PER_BLOCK (NTHREADS / 32)
#define NWARPS    (NBLOCKS * WARPS_PER_BLOCK)   // 9472 -> 105-106 contiguous rows per warp

// Per-block partial sums (every block writes its slot every launch -> no zeroing).
__device__ float g_partials[NBLOCKS];
// Ticket counter for last-block-done reduction; reset by the last block each launch.
__device__ int g_count = 0;

__device__ __forceinline__ float warp_sum(float s) {
    #pragma unroll
    for (int o = 16; o; o >>= 1) s += __shfl_xor_sync(0xffffffffu, s, o);
    return s;
}

// Process rows (rowbase, rowbase+1). Returns the per-lane replicated hinge
// contribution: lanes 0-15 hold hinge(row0), lanes 16-31 hold hinge(row1).
__device__ __forceinline__ float hinge_pair(
    const float4* __restrict__ x4, const float4* __restrict__ c4,
    unsigned rowbase, int lab0, int lab1, int lane, float margin)
{
    float4 xv0 = __ldcs(&x4[rowbase * 32u + lane]);
    float4 xv1 = __ldcs(&x4[(rowbase + 1u) * 32u + lane]);
    float4 cv0 = __ldg(&c4[(unsigned)lab0 * 32u + lane]);
    float4 cv1 = __ldg(&c4[(unsigned)lab1 * 32u + lane]);

    float a0 = xv0.x - cv0.x, a1 = xv0.y - cv0.y, a2 = xv0.z - cv0.z, a3 = xv0.w - cv0.w;
    float b0 = xv1.x - cv1.x, b1 = xv1.y - cv1.y, b2 = xv1.z - cv1.z, b3 = xv1.w - cv1.w;
    float s0 = a0*a0 + a1*a1 + a2*a2 + a3*a3;
    float s1 = b0*b0 + b1*b1 + b2*b2 + b3*b3;

    // Paired reduction: cross-half exchange then 4 butterflies within halves.
    // 5 shuffles for 2 rows.
    const bool hi = (lane & 16) != 0;
    float send = hi ? s0 : s1;
    float recv = __shfl_xor_sync(0xffffffffu, send, 16);
    float z = (hi ? s1 : s0) + recv;
    #pragma unroll
    for (int o = 8; o; o >>= 1) z += __shfl_xor_sync(0xffffffffu, z, o);
    return fmaxf(z - margin, 0.0f);
}

__global__ __launch_bounds__(NTHREADS) void hinge_fused_kernel(
    const float* __restrict__ x,
    const int* __restrict__ labels,
    const float* __restrict__ centers,
    float* __restrict__ out)
{
    const int lane = threadIdx.x & 31;
    const int wid  = threadIdx.x >> 5;
    const int gw   = blockIdx.x * WARPS_PER_BLOCK + wid;

    const float4* __restrict__ x4 = reinterpret_cast<const float4*>(x);
    const float4* __restrict__ c4 = reinterpret_cast<const float4*>(centers);

    // margin = ||centers[0] - centers[1]|| / 10 (tiny, L1-hit)
    float4 ca = __ldg(&c4[lane]);
    float4 cb = __ldg(&c4[32 + lane]);
    float md0 = ca.x - cb.x, md1 = ca.y - cb.y, md2 = ca.z - cb.z, md3 = ca.w - cb.w;
    const float margin = sqrtf(warp_sum(md0*md0 + md1*md1 + md2*md2 + md3*md3)) * 0.1f;

    // Balanced contiguous partition: warp gw owns rows [rbeg, rend), 105-106 rows.
    const unsigned rbeg = (unsigned)(((unsigned long long)gw       * BATCH) / NWARPS);
    const unsigned rend = (unsigned)(((unsigned long long)(gw + 1) * BATCH) / NWARPS);

    float acc = 0.0f;   // 16x-replicated hinge sums; rescaled by 1/16 at the end

    // Preload labels for the first 32-row sub-tile.
    unsigned tbase = rbeg;
    int mylab = (tbase + lane < rend) ? __ldcs(&labels[tbase + lane]) : 0;

    while (tbase < rend) {
        const unsigned nextbase = tbase + 32u;
        // Prefetch next sub-tile's labels so the label->center dependency is
        // overlapped with this sub-tile's work.
        int nextlab = 0;
        if (nextbase + lane < rend) nextlab = __ldcs(&labels[nextbase + lane]);

        const unsigned cnt = min(32u, rend - tbase);

        if (cnt == 32u) {
            // Fast path: fully unrolled 16 pairs.
            #pragma unroll 2
            for (int k = 0; k < 16; k++) {
                const int lab0 = __shfl_sync(0xffffffffu, mylab, 2 * k);
                const int lab1 = __shfl_sync(0xffffffffu, mylab, 2 * k + 1);
                acc += hinge_pair(x4, c4, tbase + 2u * k, lab0, lab1, lane, margin);
            }
        } else {
            // Tail sub-tile: dynamic pair loop + optional single row.
            const unsigned pairs = cnt >> 1;
            for (unsigned k = 0; k < pairs; k++) {
                const int lab0 = __shfl_sync(0xffffffffu, mylab, 2 * k);
                const int lab1 = __shfl_sync(0xffffffffu, mylab, 2 * k + 1);
                acc += hinge_pair(x4, c4, tbase + 2u * k, lab0, lab1, lane, margin);
            }
            if (cnt & 1u) {
                const int lab = __shfl_sync(0xffffffffu, mylab, cnt - 1);
                float4 xv = __ldcs(&x4[(tbase + cnt - 1u) * 32u + lane]);
                float4 cv = __ldg (&c4[(unsigned)lab * 32u + lane]);
                float t0 = xv.x - cv.x, t1 = xv.y - cv.y, t2 = xv.z - cv.z, t3 = xv.w - cv.w;
                float s = warp_sum(t0*t0 + t1*t1 + t2*t2 + t3*t3);  // replicated x32
                acc += fmaxf(s - margin, 0.0f) * 0.5f;              // 32 * 0.5 = 16 copies
            }
        }

        mylab = nextlab;
        tbase = nextbase;
    }

    // warp_sum(acc) = 16 * (true warp hinge sum); exact 1/16 rescale.
    const float wacc = warp_sum(acc) * 0.0625f;

    // Block reduce.
    __shared__ float smem[WARPS_PER_BLOCK];
    __shared__ bool is_last;
    if (lane == 0) smem[wid] = wacc;
    __syncthreads();
    if (threadIdx.x == 0) {
        float s = 0.0f;
        #pragma unroll
        for (int i = 0; i < WARPS_PER_BLOCK; i++) s += smem[i];
        g_partials[blockIdx.x] = s;
        __threadfence();
        int ticket = atomicAdd(&g_count, 1);
        is_last = (ticket == NBLOCKS - 1);
    }
    __syncthreads();

    // Last block reduces all partials (f64, fixed order) and writes the scalar.
    if (is_last) {
        __shared__ double sm[NTHREADS];
        double s = 0.0;
        for (int i = threadIdx.x; i < NBLOCKS; i += NTHREADS)
            s += (double)g_partials[i];
        sm[threadIdx.x] = s;
        __syncthreads();
        #pragma unroll
        for (int o = NTHREADS / 2; o; o >>= 1) {
            if (threadIdx.x < o) sm[threadIdx.x] += sm[threadIdx.x + o];
            __syncthreads();
        }
        if (threadIdx.x == 0) {
            out[0] = (float)(sm[0] / (4.0 * (double)BATCH));
            g_count = 0;   // reset for next launch / graph replay
        }
    }
}

extern "C" void kernel_launch(void* const* d_in, const int* in_sizes, int n_in,
                              void* d_out, int out_size)
{
    const float* x       = (const float*)d_in[0];   // [1e6, 128] f32
    const int*   labels  = (const int*)  d_in[1];   // [1e6] i32
    const float* centers = (const float*)d_in[2];   // [1000, 128] f32
    float*       out     = (float*)d_out;           // scalar f32

    hinge_fused_kernel<<<NBLOCKS, NTHREADS>>>(x, labels, centers, out);
}

// round 6
// speedup vs baseline: 1.0889x; 1.0889x over previous
#include <cuda_runtime.h>
#include <cuda_bf16.h>

#define BATCH     1000000
#define FEAT      128
#define NCLASS    1000
#define NTHREADS  256
#define NBLOCKS   1184                      // 148 SMs * 8 blocks -> one full resident wave at 32 regs
#define WARPS_PER_BLOCK (NTHREADS / 32)
#define NWARPS    (NBLOCKS * WARPS_PER_BLOCK)   // 9472 -> 105-106 contiguous rows per warp

// Per-block partial sums (every block writes its slot every launch -> no zeroing).
__device__ float g_partials[NBLOCKS];
// Ticket counter for last-block-done reduction; reset by the last block each launch.
__device__ int g_count = 0;

__device__ __forceinline__ float warp_sum(float s) {
    #pragma unroll
    for (int o = 16; o; o >>= 1) s += __shfl_xor_sync(0xffffffffu, s, o);
    return s;
}

__global__ __launch_bounds__(NTHREADS) void hinge_fused_kernel(
    const float* __restrict__ x,
    const int* __restrict__ labels,
    const float* __restrict__ centers,
    float* __restrict__ out)
{
    const int lane = threadIdx.x & 31;
    const int wid  = threadIdx.x >> 5;
    const int gw   = blockIdx.x * WARPS_PER_BLOCK + wid;

    const float4* __restrict__ x4 = reinterpret_cast<const float4*>(x);
    const float4* __restrict__ c4 = reinterpret_cast<const float4*>(centers);

    // margin = ||centers[0] - centers[1]|| / 10 (tiny, L1-hit)
    float4 ca = __ldg(&c4[lane]);
    float4 cb = __ldg(&c4[32 + lane]);
    float md0 = ca.x - cb.x, md1 = ca.y - cb.y, md2 = ca.z - cb.z, md3 = ca.w - cb.w;
    const float margin = sqrtf(warp_sum(md0*md0 + md1*md1 + md2*md2 + md3*md3)) * 0.1f;

    // Balanced contiguous partition: warp gw owns rows [rbeg, rend), 105-106 rows.
    // Contiguous rows -> this warp's labels sit in ~4 cache lines (broadcast
    // label loads below are L1 hits) and its x stream is one 53 KB sweep.
    const unsigned rbeg = (unsigned)(((unsigned long long)gw       * BATCH) / NWARPS);
    const unsigned rend = (unsigned)(((unsigned long long)(gw + 1) * BATCH) / NWARPS);

    float acc = 0.0f;   // 16x-replicated hinge sums; rescaled by 1/16 at the end

    // Flat R2-style loop over row pairs -- no sub-tile machinery, minimal regs.
    unsigned r = rbeg;
    for (; r + 1 < rend; r += 2) {
        const int lab0 = __ldg(&labels[r]);
        const int lab1 = __ldg(&labels[r + 1]);

        float4 xv0 = __ldcs(&x4[r * 32u + lane]);
        float4 xv1 = __ldcs(&x4[(r + 1u) * 32u + lane]);
        float4 cv0 = __ldg(&c4[(unsigned)lab0 * 32u + lane]);
        float4 cv1 = __ldg(&c4[(unsigned)lab1 * 32u + lane]);

        float a0 = xv0.x - cv0.x, a1 = xv0.y - cv0.y, a2 = xv0.z - cv0.z, a3 = xv0.w - cv0.w;
        float b0 = xv1.x - cv1.x, b1 = xv1.y - cv1.y, b2 = xv1.z - cv1.z, b3 = xv1.w - cv1.w;
        float s0 = a0*a0 + a1*a1 + a2*a2 + a3*a3;
        float s1 = b0*b0 + b1*b1 + b2*b2 + b3*b3;

        // Paired reduction: one cross-half exchange, then 4 butterflies within
        // halves. 5 shuffles for 2 rows; result replicated x16 per half.
        const bool hi = (lane & 16) != 0;
        float send = hi ? s0 : s1;
        float recv = __shfl_xor_sync(0xffffffffu, send, 16);
        float z = (hi ? s1 : s0) + recv;
        #pragma unroll
        for (int o = 8; o; o >>= 1) z += __shfl_xor_sync(0xffffffffu, z, o);
        acc += fmaxf(z - margin, 0.0f);
    }
    if (r < rend) {  // odd leftover row (ranges are 105 or 106 rows)
        const int lab = __ldg(&labels[r]);
        float4 xv = __ldcs(&x4[r * 32u + lane]);
        float4 cv = __ldg (&c4[(unsigned)lab * 32u + lane]);
        float t0 = xv.x - cv.x, t1 = xv.y - cv.y, t2 = xv.z - cv.z, t3 = xv.w - cv.w;
        float s = warp_sum(t0*t0 + t1*t1 + t2*t2 + t3*t3);  // replicated x32
        acc += fmaxf(s - margin, 0.0f) * 0.5f;              // 32 * 0.5 = 16 copies
    }

    // warp_sum(acc) = 16 * (true warp hinge sum); exact 1/16 rescale.
    const float wacc = warp_sum(acc) * 0.0625f;

    // Block reduce.
    __shared__ float smem[WARPS_PER_BLOCK];
    __shared__ bool is_last;
    if (lane == 0) smem[wid] = wacc;
    __syncthreads();
    if (threadIdx.x == 0) {
        float s = 0.0f;
        #pragma unroll
        for (int i = 0; i < WARPS_PER_BLOCK; i++) s += smem[i];
        g_partials[blockIdx.x] = s;
        __threadfence();
        int ticket = atomicAdd(&g_count, 1);
        is_last = (ticket == NBLOCKS - 1);
    }
    __syncthreads();

    // Last block reduces all partials (f64, fixed order) and writes the scalar.
    if (is_last) {
        __shared__ double sm[NTHREADS];
        double s = 0.0;
        for (int i = threadIdx.x; i < NBLOCKS; i += NTHREADS)
            s += (double)g_partials[i];
        sm[threadIdx.x] = s;
        __syncthreads();
        #pragma unroll
        for (int o = NTHREADS / 2; o; o >>= 1) {
            if (threadIdx.x < o) sm[threadIdx.x] += sm[threadIdx.x + o];
            __syncthreads();
        }
        if (threadIdx.x == 0) {
            out[0] = (float)(sm[0] / (4.0 * (double)BATCH));
            g_count = 0;   // reset for next launch / graph replay
        }
    }
}

extern "C" void kernel_launch(void* const* d_in, const int* in_sizes, int n_in,
                              void* d_out, int out_size)
{
    const float* x       = (const float*)d_in[0];   // [1e6, 128] f32
    const int*   labels  = (const int*)  d_in[1];   // [1e6] i32
    const float* centers = (const float*)d_in[2];   // [1000, 128] f32
    float*       out     = (float*)d_out;           // scalar f32

    hinge_fused_kernel<<<NBLOCKS, NTHREADS>>>(x, labels, centers, out);
}